// round 1
// baseline (speedup 1.0000x reference)
#include <cuda_runtime.h>
#include <math.h>

// ---------------- problem constants ----------------
#define BATCH 8
#define L1 2048
#define L2 2048
#define D1 1024
#define D2 768
#define EDIM 1024
#define ROWS1 (BATCH * L1)          // 16384
#define ROWS2 (BATCH * L2)          // 16384

// ---------------- scratch (device globals; no allocation) ----------------
__device__ float g_x1[ROWS1 * D1];          // 64 MB  normalized modality1
__device__ float g_x2[ROWS2 * D2];          // 48 MB  normalized modality2
__device__ float g_q[ROWS1 * EDIM];         // 64 MB
__device__ float g_k[ROWS2 * EDIM];         // 64 MB
__device__ float g_v[ROWS2 * EDIM];         // 64 MB
__device__ float g_s[(size_t)BATCH * L1 * L2];   // 512 MB  scores / attn
__device__ float g_ctx[ROWS1 * EDIM];       // 64 MB

// ---------------- block reductions ----------------
__device__ __forceinline__ float blockReduceSum256(float v) {
    __shared__ float sh[8];
    int lane = threadIdx.x & 31, w = threadIdx.x >> 5;
    #pragma unroll
    for (int o = 16; o > 0; o >>= 1) v += __shfl_xor_sync(0xffffffffu, v, o);
    __syncthreads();                 // protect sh reuse across calls
    if (lane == 0) sh[w] = v;
    __syncthreads();
    if (w == 0) {
        v = (lane < 8) ? sh[lane] : 0.f;
        #pragma unroll
        for (int o = 4; o > 0; o >>= 1) v += __shfl_xor_sync(0xffffffffu, v, o);
        if (lane == 0) sh[0] = v;
    }
    __syncthreads();
    return sh[0];
}

__device__ __forceinline__ float blockReduceMax256(float v) {
    __shared__ float sh[8];
    int lane = threadIdx.x & 31, w = threadIdx.x >> 5;
    #pragma unroll
    for (int o = 16; o > 0; o >>= 1) v = fmaxf(v, __shfl_xor_sync(0xffffffffu, v, o));
    __syncthreads();
    if (lane == 0) sh[w] = v;
    __syncthreads();
    if (w == 0) {
        v = (lane < 8) ? sh[lane] : -INFINITY;
        #pragma unroll
        for (int o = 4; o > 0; o >>= 1) v = fmaxf(v, __shfl_xor_sync(0xffffffffu, v, o));
        if (lane == 0) sh[0] = v;
    }
    __syncthreads();
    return sh[0];
}

// ---------------- layernorm: one block (256 thr) per row ----------------
template<int NV>
__global__ __launch_bounds__(256)
void layernorm_kernel(const float* __restrict__ x, const float* __restrict__ g,
                      const float* __restrict__ b, float* __restrict__ y, int D) {
    const size_t row = blockIdx.x;
    const float* xr = x + row * (size_t)D;
    float*       yr = y + row * (size_t)D;
    float v[NV];
    float s = 0.f;
    #pragma unroll
    for (int j = 0; j < NV; j++) {
        v[j] = xr[threadIdx.x + j * 256];
        s += v[j];
    }
    const float mu = blockReduceSum256(s) * (1.f / (float)D);
    float sq = 0.f;
    #pragma unroll
    for (int j = 0; j < NV; j++) {
        float d = v[j] - mu;
        sq += d * d;
    }
    const float rstd = rsqrtf(blockReduceSum256(sq) * (1.f / (float)D) + 1e-5f);
    #pragma unroll
    for (int j = 0; j < NV; j++) {
        int idx = threadIdx.x + j * 256;
        yr[idx] = (v[j] - mu) * rstd * g[idx] + b[idx];
    }
}

// ---------------- softmax over rows of length 2048 ----------------
__global__ __launch_bounds__(256)
void softmax_kernel(float* __restrict__ s) {
    const size_t row = blockIdx.x;
    float* p = s + row * (size_t)L2;
    float v[8];
    float m = -INFINITY;
    #pragma unroll
    for (int j = 0; j < 8; j++) {
        v[j] = p[threadIdx.x + j * 256];
        m = fmaxf(m, v[j]);
    }
    m = blockReduceMax256(m);
    float sum = 0.f;
    #pragma unroll
    for (int j = 0; j < 8; j++) {
        v[j] = __expf(v[j] - m);
        sum += v[j];
    }
    const float inv = 1.f / blockReduceSum256(sum);
    #pragma unroll
    for (int j = 0; j < 8; j++) {
        p[threadIdx.x + j * 256] = v[j] * inv;
    }
}

// ---------------- 128x128x8 SGEMM, 8x8 register tile, 256 threads ----------------
// C[M,N] = scale * (A[M,K] @ B) + bias, batched via blockIdx.z strides.
// BT=false: B is [K,N] row-major (NN).  BT=true: B is [N,K] row-major (NT, i.e. B^T).
// All of M,N must be multiples of 128, K a multiple of 8 (true for every call here).
template<bool BT>
__global__ __launch_bounds__(256)
void sgemm_kernel(const float* __restrict__ A, const float* __restrict__ B,
                  const float* __restrict__ bias, float* __restrict__ C,
                  int M, int N, int K, float scale,
                  long long sA, long long sB, long long sC) {
    A += (long long)blockIdx.z * sA;
    B += (long long)blockIdx.z * sB;
    C += (long long)blockIdx.z * sC;

    __shared__ float As[8][128];
    __shared__ float Bs[8][128];

    const int tid = threadIdx.x;
    const int tx = tid & 15;         // N-dir thread coord (0..15)
    const int ty = tid >> 4;         // M-dir thread coord (0..15)
    const int row0 = blockIdx.y * 128;
    const int col0 = blockIdx.x * 128;

    // A-tile load map: 128 rows x 8 cols, one float4 per thread (transposed store)
    const int ar = tid >> 1;         // 0..127
    const int ac = (tid & 1) * 4;    // 0 or 4
    // B-tile NN load map: 8 rows x 128 cols, one float4 per thread
    const int bk = tid >> 5;         // 0..7
    const int bn = (tid & 31) * 4;   // 0..124

    float acc[8][8];
    #pragma unroll
    for (int i = 0; i < 8; i++)
        #pragma unroll
        for (int j = 0; j < 8; j++) acc[i][j] = 0.f;

    for (int k0 = 0; k0 < K; k0 += 8) {
        float4 a4 = *(const float4*)(A + (size_t)(row0 + ar) * K + k0 + ac);
        As[ac + 0][ar] = a4.x;
        As[ac + 1][ar] = a4.y;
        As[ac + 2][ar] = a4.z;
        As[ac + 3][ar] = a4.w;
        if (BT) {
            // B is [N,K]; tile rows = output cols
            float4 b4 = *(const float4*)(B + (size_t)(col0 + ar) * K + k0 + ac);
            Bs[ac + 0][ar] = b4.x;
            Bs[ac + 1][ar] = b4.y;
            Bs[ac + 2][ar] = b4.z;
            Bs[ac + 3][ar] = b4.w;
        } else {
            float4 b4 = *(const float4*)(B + (size_t)(k0 + bk) * N + col0 + bn);
            *(float4*)&Bs[bk][bn] = b4;
        }
        __syncthreads();

        #pragma unroll
        for (int kk = 0; kk < 8; kk++) {
            float a_[8], b_[8];
            *(float4*)&a_[0] = *(const float4*)&As[kk][ty * 8];
            *(float4*)&a_[4] = *(const float4*)&As[kk][ty * 8 + 4];
            *(float4*)&b_[0] = *(const float4*)&Bs[kk][tx * 8];
            *(float4*)&b_[4] = *(const float4*)&Bs[kk][tx * 8 + 4];
            #pragma unroll
            for (int i = 0; i < 8; i++)
                #pragma unroll
                for (int j = 0; j < 8; j++)
                    acc[i][j] = fmaf(a_[i], b_[j], acc[i][j]);
        }
        __syncthreads();
    }

    #pragma unroll
    for (int i = 0; i < 8; i++) {
        const size_t r = row0 + ty * 8 + i;
        #pragma unroll
        for (int j = 0; j < 8; j += 4) {
            const int c = col0 + tx * 8 + j;
            float4 o;
            o.x = acc[i][j + 0] * scale;
            o.y = acc[i][j + 1] * scale;
            o.z = acc[i][j + 2] * scale;
            o.w = acc[i][j + 3] * scale;
            if (bias != nullptr) {
                o.x += bias[c + 0];
                o.y += bias[c + 1];
                o.z += bias[c + 2];
                o.w += bias[c + 3];
            }
            *(float4*)(C + r * (size_t)N + c) = o;
        }
    }
}

// ---------------- launch ----------------
extern "C" void kernel_launch(void* const* d_in, const int* in_sizes, int n_in,
                              void* d_out, int out_size) {
    const float* modality1 = (const float*)d_in[0];
    const float* modality2 = (const float*)d_in[1];
    const float* ln1_g = (const float*)d_in[2];
    const float* ln1_b = (const float*)d_in[3];
    const float* ln2_g = (const float*)d_in[4];
    const float* ln2_b = (const float*)d_in[5];
    const float* Wq = (const float*)d_in[6];
    const float* bq = (const float*)d_in[7];
    const float* Wk = (const float*)d_in[8];
    const float* bk = (const float*)d_in[9];
    const float* Wv = (const float*)d_in[10];
    const float* bv = (const float*)d_in[11];
    const float* Wo = (const float*)d_in[12];
    const float* bo = (const float*)d_in[13];
    float* out = (float*)d_out;

    float *x1, *x2, *q, *k, *v, *s, *ctx;
    cudaGetSymbolAddress((void**)&x1, g_x1);
    cudaGetSymbolAddress((void**)&x2, g_x2);
    cudaGetSymbolAddress((void**)&q, g_q);
    cudaGetSymbolAddress((void**)&k, g_k);
    cudaGetSymbolAddress((void**)&v, g_v);
    cudaGetSymbolAddress((void**)&s, g_s);
    cudaGetSymbolAddress((void**)&ctx, g_ctx);

    const float scaling = 1.0f / 32.0f;   // E^-0.5, E=1024

    // 1) layernorms
    layernorm_kernel<4><<<ROWS1, 256>>>(modality1, ln1_g, ln1_b, x1, D1);
    layernorm_kernel<3><<<ROWS2, 256>>>(modality2, ln2_g, ln2_b, x2, D2);

    // 2) Q/K/V projections (flattened over batch)
    {
        dim3 grid(EDIM / 128, ROWS1 / 128, 1);
        sgemm_kernel<false><<<grid, 256>>>(x1, Wq, bq, q, ROWS1, EDIM, D1, 1.f, 0, 0, 0);
    }
    {
        dim3 grid(EDIM / 128, ROWS2 / 128, 1);
        sgemm_kernel<false><<<grid, 256>>>(x2, Wk, bk, k, ROWS2, EDIM, D2, 1.f, 0, 0, 0);
        sgemm_kernel<false><<<grid, 256>>>(x2, Wv, bv, v, ROWS2, EDIM, D2, 1.f, 0, 0, 0);
    }

    // 3) scores = scaling * Q @ K^T   (batched NT)
    {
        dim3 grid(L2 / 128, L1 / 128, BATCH);
        sgemm_kernel<true><<<grid, 256>>>(q, k, nullptr, s, L1, L2, EDIM, scaling,
                                          (long long)L1 * EDIM, (long long)L2 * EDIM,
                                          (long long)L1 * L2);
    }

    // 4) softmax rows
    softmax_kernel<<<BATCH * L1, 256>>>(s);

    // 5) ctx = attn @ V   (batched NN)
    {
        dim3 grid(EDIM / 128, L1 / 128, BATCH);
        sgemm_kernel<false><<<grid, 256>>>(s, v, nullptr, ctx, L1, EDIM, L2, 1.f,
                                           (long long)L1 * L2, (long long)L2 * EDIM,
                                           (long long)L1 * EDIM);
    }

    // 6) out = ctx @ Wo + bo
    {
        dim3 grid(D1 / 128, ROWS1 / 128, 1);
        sgemm_kernel<false><<<grid, 256>>>(ctx, Wo, bo, out, ROWS1, D1, EDIM, 1.f, 0, 0, 0);
    }
}

// round 3
// speedup vs baseline: 3.3261x; 3.3261x over previous
#include <cuda_runtime.h>
#include <math.h>
#include <stdint.h>

// ---------------- problem constants ----------------
#define BATCH 8
#define L1 2048
#define L2 2048
#define D1 1024
#define D2 768
#define EDIM 1024
#define ROWS1 (BATCH * L1)          // 16384
#define ROWS2 (BATCH * L2)          // 16384

// ---------------- scratch (device globals; no allocation) ----------------
__device__ float g_x1[ROWS1 * D1];
__device__ float g_x2[ROWS2 * D2];
__device__ float g_q[ROWS1 * EDIM];
__device__ float g_k[ROWS2 * EDIM];
__device__ float g_v[ROWS2 * EDIM];
__device__ float g_vT[ROWS2 * EDIM];             // per-batch V^T [E, L2]
__device__ float g_s[(size_t)BATCH * L1 * L2];   // scores / attn
__device__ float g_ctx[ROWS1 * EDIM];
__device__ float g_wqT[EDIM * D1];
__device__ float g_wkT[EDIM * D2];
__device__ float g_wvT[EDIM * D2];
__device__ float g_woT[D1 * EDIM];

// ---------------- helpers ----------------
static __device__ __forceinline__ uint32_t smem_u32(const void* p) {
    uint32_t a;
    asm("{ .reg .u64 t; cvta.to.shared.u64 t, %1; cvt.u32.u64 %0, t; }" : "=r"(a) : "l"(p));
    return a;
}
static __device__ __forceinline__ float f2tf32f(float x) {
    uint32_t y; asm("cvt.rna.tf32.f32 %0, %1;" : "=r"(y) : "f"(x));
    return __uint_as_float(y);
}
static __device__ __forceinline__ void cp_async16(uint32_t saddr, const void* gptr) {
    asm volatile("cp.async.cg.shared.global [%0], [%1], 16;" :: "r"(saddr), "l"(gptr));
}
static __device__ __forceinline__ void cp_commit() {
    asm volatile("cp.async.commit_group;" ::: "memory");
}
template<int N>
static __device__ __forceinline__ void cp_wait() {
    asm volatile("cp.async.wait_group %0;" :: "n"(N) : "memory");
}

#define MMA_TF32(d, a, b) \
    asm volatile("mma.sync.aligned.m16n8k8.row.col.f32.tf32.tf32.f32 " \
        "{%0,%1,%2,%3}, {%4,%5,%6,%7}, {%8,%9}, {%0,%1,%2,%3};" \
        : "+f"((d)[0]), "+f"((d)[1]), "+f"((d)[2]), "+f"((d)[3]) \
        : "r"((a)[0]), "r"((a)[1]), "r"((a)[2]), "r"((a)[3]), \
          "r"((b)[0]), "r"((b)[1]))

// ================= tf32 mma.sync GEMM =================
// C[M,N] = scale*(A[M,K] @ B[N,K]^T) + bias ;  A,B K-major, values pre-rounded to tf32.
// BM=128, BN=128, BK=16. 128 threads = 4 warps (2x2), warp tile 64x64.
// Smem: row stride 20 words (mod 32 == 4*odd) -> conflict-free LDS.32 fragments.
#define STAGES 3
#define AW 2560                    // words per A stage (128*20)
#define STW 5120                   // words per stage (A+B)
#define GSMEM (STAGES * STW * 4)   // 61440 bytes

__global__ void __launch_bounds__(128, 2)
gemm_mma(const float* __restrict__ A, const float* __restrict__ B,
         const float* __restrict__ bias, float* __restrict__ C,
         int K, int N, float scale, int round_out,
         long long sA, long long sB, long long sC) {
    extern __shared__ uint32_t sm[];
    const uint32_t sb = smem_u32(sm);
    const int tid = threadIdx.x;
    const int lane = tid & 31, warp = tid >> 5;
    const int g = lane >> 2, t = lane & 3;
    const int m0 = (warp >> 1) * 64;       // warp M offset in tile
    const int n0 = (warp & 1) * 64;        // warp N offset in tile

    A += (long long)blockIdx.z * sA + (size_t)blockIdx.y * 128 * K;
    B += (long long)blockIdx.z * sB + (size_t)blockIdx.x * 128 * K;
    C += (long long)blockIdx.z * sC;

    // per-thread gmem/smem map for cp.async: v = tid + f*128; row=v>>2, c=v&3
    const int r_ld = tid >> 2;             // base row (0..31), +32 per f
    const int c_ld = tid & 3;              // 16B chunk in K

    float acc[4][8][4];
    #pragma unroll
    for (int i = 0; i < 4; i++)
        #pragma unroll
        for (int j = 0; j < 8; j++)
            #pragma unroll
            for (int e = 0; e < 4; e++) acc[i][j][e] = 0.f;

    const int nch = K >> 4;

    // prologue: stages 0..STAGES-2
    #pragma unroll
    for (int s = 0; s < STAGES - 1; s++) {
        const int k0 = s * 16;
        #pragma unroll
        for (int f = 0; f < 4; f++) {
            int row = r_ld + f * 32;
            cp_async16(sb + (s * STW + row * 20 + c_ld * 4) * 4,
                       A + (size_t)row * K + k0 + c_ld * 4);
            cp_async16(sb + (s * STW + AW + row * 20 + c_ld * 4) * 4,
                       B + (size_t)row * K + k0 + c_ld * 4);
        }
        cp_commit();
    }

    for (int i = 0; i < nch; i++) {
        cp_wait<STAGES - 2>();
        __syncthreads();

        // issue chunk i+STAGES-1 into stage (i-1)%STAGES
        {
            const int ic = i + STAGES - 1;
            if (ic < nch) {
                const int st = ic % STAGES;
                const int k0 = ic * 16;
                #pragma unroll
                for (int f = 0; f < 4; f++) {
                    int row = r_ld + f * 32;
                    cp_async16(sb + (st * STW + row * 20 + c_ld * 4) * 4,
                               A + (size_t)row * K + k0 + c_ld * 4);
                    cp_async16(sb + (st * STW + AW + row * 20 + c_ld * 4) * 4,
                               B + (size_t)row * K + k0 + c_ld * 4);
                }
            }
            cp_commit();
        }

        // compute chunk i
        const uint32_t* __restrict__ smA = sm + (i % STAGES) * STW;
        const uint32_t* __restrict__ smB = smA + AW;
        #pragma unroll
        for (int ks = 0; ks < 2; ks++) {
            const int kk = ks * 8;
            uint32_t af[4][4], bf[8][2];
            #pragma unroll
            for (int ii = 0; ii < 4; ii++) {
                const int mr = m0 + ii * 16 + g;
                af[ii][0] = smA[mr * 20 + kk + t];
                af[ii][1] = smA[(mr + 8) * 20 + kk + t];
                af[ii][2] = smA[mr * 20 + kk + t + 4];
                af[ii][3] = smA[(mr + 8) * 20 + kk + t + 4];
            }
            #pragma unroll
            for (int jj = 0; jj < 8; jj++) {
                const int nr = n0 + jj * 8 + g;
                bf[jj][0] = smB[nr * 20 + kk + t];
                bf[jj][1] = smB[nr * 20 + kk + t + 4];
            }
            #pragma unroll
            for (int ii = 0; ii < 4; ii++)
                #pragma unroll
                for (int jj = 0; jj < 8; jj++)
                    MMA_TF32(acc[ii][jj], af[ii], bf[jj]);
        }
        __syncthreads();
    }

    // epilogue
    const int row_base = blockIdx.y * 128 + m0 + g;
    const int col_base = blockIdx.x * 128 + n0 + t * 2;
    #pragma unroll
    for (int ii = 0; ii < 4; ii++) {
        #pragma unroll
        for (int jj = 0; jj < 8; jj++) {
            const int col = col_base + jj * 8;
            float bx = 0.f, by = 0.f;
            if (bias) { bx = __ldg(bias + col); by = __ldg(bias + col + 1); }
            float2 v0, v1;
            v0.x = acc[ii][jj][0] * scale + bx;
            v0.y = acc[ii][jj][1] * scale + by;
            v1.x = acc[ii][jj][2] * scale + bx;
            v1.y = acc[ii][jj][3] * scale + by;
            if (round_out) {
                v0.x = f2tf32f(v0.x); v0.y = f2tf32f(v0.y);
                v1.x = f2tf32f(v1.x); v1.y = f2tf32f(v1.y);
            }
            *(float2*)(C + (size_t)(row_base + ii * 16) * N + col) = v0;
            *(float2*)(C + (size_t)(row_base + ii * 16 + 8) * N + col) = v1;
        }
    }
}

// ================= layernorm / softmax / transpose =================
static __device__ __forceinline__ float blockReduceSum256(float v) {
    __shared__ float sh[8];
    int lane = threadIdx.x & 31, w = threadIdx.x >> 5;
    #pragma unroll
    for (int o = 16; o > 0; o >>= 1) v += __shfl_xor_sync(0xffffffffu, v, o);
    __syncthreads();
    if (lane == 0) sh[w] = v;
    __syncthreads();
    if (w == 0) {
        v = (lane < 8) ? sh[lane] : 0.f;
        #pragma unroll
        for (int o = 4; o > 0; o >>= 1) v += __shfl_xor_sync(0xffffffffu, v, o);
        if (lane == 0) sh[0] = v;
    }
    __syncthreads();
    return sh[0];
}
static __device__ __forceinline__ float blockReduceMax256(float v) {
    __shared__ float sh[8];
    int lane = threadIdx.x & 31, w = threadIdx.x >> 5;
    #pragma unroll
    for (int o = 16; o > 0; o >>= 1) v = fmaxf(v, __shfl_xor_sync(0xffffffffu, v, o));
    __syncthreads();
    if (lane == 0) sh[w] = v;
    __syncthreads();
    if (w == 0) {
        v = (lane < 8) ? sh[lane] : -INFINITY;
        #pragma unroll
        for (int o = 4; o > 0; o >>= 1) v = fmaxf(v, __shfl_xor_sync(0xffffffffu, v, o));
        if (lane == 0) sh[0] = v;
    }
    __syncthreads();
    return sh[0];
}

template<int NV>
__global__ __launch_bounds__(256)
void layernorm_kernel(const float* __restrict__ x, const float* __restrict__ g,
                      const float* __restrict__ b, float* __restrict__ y, int D) {
    const size_t row = blockIdx.x;
    const float* xr = x + row * (size_t)D;
    float*       yr = y + row * (size_t)D;
    float v[NV];
    float s = 0.f;
    #pragma unroll
    for (int j = 0; j < NV; j++) { v[j] = xr[threadIdx.x + j * 256]; s += v[j]; }
    const float mu = blockReduceSum256(s) * (1.f / (float)D);
    float sq = 0.f;
    #pragma unroll
    for (int j = 0; j < NV; j++) { float d = v[j] - mu; sq += d * d; }
    const float rstd = rsqrtf(blockReduceSum256(sq) * (1.f / (float)D) + 1e-5f);
    #pragma unroll
    for (int j = 0; j < NV; j++) {
        int idx = threadIdx.x + j * 256;
        yr[idx] = f2tf32f((v[j] - mu) * rstd * g[idx] + b[idx]);   // tf32-round for mma
    }
}

__global__ __launch_bounds__(256)
void softmax_kernel(float* __restrict__ s) {
    const size_t row = blockIdx.x;
    float* p = s + row * (size_t)L2;
    float v[8];
    float m = -INFINITY;
    #pragma unroll
    for (int j = 0; j < 8; j++) { v[j] = p[threadIdx.x + j * 256]; m = fmaxf(m, v[j]); }
    m = blockReduceMax256(m);
    float sum = 0.f;
    #pragma unroll
    for (int j = 0; j < 8; j++) { v[j] = __expf(v[j] - m); sum += v[j]; }
    const float inv = 1.f / blockReduceSum256(sum);
    #pragma unroll
    for (int j = 0; j < 8; j++) p[threadIdx.x + j * 256] = f2tf32f(v[j] * inv);
}

// out[C,R] = in[R,C]^T (tf32-rounded), batched via z
__global__ __launch_bounds__(256)
void transpose_kernel(const float* __restrict__ in, float* __restrict__ out,
                      int R, int C, long long sIn, long long sOut) {
    __shared__ float tb[32][33];
    in  += (long long)blockIdx.z * sIn;
    out += (long long)blockIdx.z * sOut;
    const int r0 = blockIdx.y * 32, c0 = blockIdx.x * 32;
    const int tx = threadIdx.x & 31, ty = threadIdx.x >> 5;
    #pragma unroll
    for (int k = 0; k < 32; k += 8)
        tb[ty + k][tx] = in[(size_t)(r0 + ty + k) * C + c0 + tx];
    __syncthreads();
    #pragma unroll
    for (int k = 0; k < 32; k += 8)
        out[(size_t)(c0 + ty + k) * R + r0 + tx] = f2tf32f(tb[tx][ty + k]);
}

// ================= launch =================
extern "C" void kernel_launch(void* const* d_in, const int* in_sizes, int n_in,
                              void* d_out, int out_size) {
    const float* modality1 = (const float*)d_in[0];
    const float* modality2 = (const float*)d_in[1];
    const float* ln1_g = (const float*)d_in[2];
    const float* ln1_b = (const float*)d_in[3];
    const float* ln2_g = (const float*)d_in[4];
    const float* ln2_b = (const float*)d_in[5];
    const float* Wq = (const float*)d_in[6];
    const float* bq = (const float*)d_in[7];
    const float* Wk = (const float*)d_in[8];
    const float* bk = (const float*)d_in[9];
    const float* Wv = (const float*)d_in[10];
    const float* bv = (const float*)d_in[11];
    const float* Wo = (const float*)d_in[12];
    const float* bo = (const float*)d_in[13];
    float* out = (float*)d_out;

    float *x1, *x2, *q, *k, *v, *vT, *s, *ctx, *wqT, *wkT, *wvT, *woT;
    cudaGetSymbolAddress((void**)&x1, g_x1);
    cudaGetSymbolAddress((void**)&x2, g_x2);
    cudaGetSymbolAddress((void**)&q, g_q);
    cudaGetSymbolAddress((void**)&k, g_k);
    cudaGetSymbolAddress((void**)&v, g_v);
    cudaGetSymbolAddress((void**)&vT, g_vT);
    cudaGetSymbolAddress((void**)&s, g_s);
    cudaGetSymbolAddress((void**)&ctx, g_ctx);
    cudaGetSymbolAddress((void**)&wqT, g_wqT);
    cudaGetSymbolAddress((void**)&wkT, g_wkT);
    cudaGetSymbolAddress((void**)&wvT, g_wvT);
    cudaGetSymbolAddress((void**)&woT, g_woT);

    cudaFuncSetAttribute(gemm_mma, cudaFuncAttributeMaxDynamicSharedMemorySize, GSMEM);

    const float scaling = 1.0f / 32.0f;   // E^-0.5

    // 1) layernorms (tf32-rounded outputs)
    layernorm_kernel<4><<<ROWS1, 256>>>(modality1, ln1_g, ln1_b, x1, D1);
    layernorm_kernel<3><<<ROWS2, 256>>>(modality2, ln2_g, ln2_b, x2, D2);

    // 2) weight transposes -> K-major [N,K], tf32-rounded
    transpose_kernel<<<dim3(EDIM / 32, D1 / 32, 1), 256>>>(Wq, wqT, D1, EDIM, 0, 0);
    transpose_kernel<<<dim3(EDIM / 32, D2 / 32, 1), 256>>>(Wk, wkT, D2, EDIM, 0, 0);
    transpose_kernel<<<dim3(EDIM / 32, D2 / 32, 1), 256>>>(Wv, wvT, D2, EDIM, 0, 0);
    transpose_kernel<<<dim3(D1 / 32, EDIM / 32, 1), 256>>>(Wo, woT, EDIM, D1, 0, 0);

    // 3) Q/K/V projections (round outputs: feed later GEMMs)
    gemm_mma<<<dim3(EDIM / 128, ROWS1 / 128, 1), 128, GSMEM>>>(
        x1, wqT, bq, q, D1, EDIM, 1.f, 1, 0, 0, 0);
    gemm_mma<<<dim3(EDIM / 128, ROWS2 / 128, 1), 128, GSMEM>>>(
        x2, wkT, bk, k, D2, EDIM, 1.f, 1, 0, 0, 0);
    gemm_mma<<<dim3(EDIM / 128, ROWS2 / 128, 1), 128, GSMEM>>>(
        x2, wvT, bv, v, D2, EDIM, 1.f, 1, 0, 0, 0);

    // 4) scores = scaling * Q @ K^T (batched; no rounding — softmax follows)
    gemm_mma<<<dim3(L2 / 128, L1 / 128, BATCH), 128, GSMEM>>>(
        q, k, nullptr, s, EDIM, L2, scaling, 0,
        (long long)L1 * EDIM, (long long)L2 * EDIM, (long long)L1 * L2);

    // 5) softmax rows (tf32-rounded output)
    softmax_kernel<<<BATCH * L1, 256>>>(s);

    // 6) V^T per batch -> [E, L2] (tf32-rounded)
    transpose_kernel<<<dim3(EDIM / 32, L2 / 32, BATCH), 256>>>(
        v, vT, L2, EDIM, (long long)L2 * EDIM, (long long)EDIM * L2);

    // 7) ctx = attn @ V (rounded output: feeds final GEMM)
    gemm_mma<<<dim3(EDIM / 128, L1 / 128, BATCH), 128, GSMEM>>>(
        s, vT, nullptr, ctx, L2, EDIM, 1.f, 1,
        (long long)L1 * L2, (long long)EDIM * L2, (long long)L1 * EDIM);

    // 8) out = ctx @ Wo + bo (fp32 output, no rounding)
    gemm_mma<<<dim3(D1 / 128, ROWS1 / 128, 1), 128, GSMEM>>>(
        ctx, woT, bo, out, EDIM, D1, 1.f, 0, 0, 0, 0);
}